// round 2
// baseline (speedup 1.0000x reference)
#include <cuda_runtime.h>
#include <math_constants.h>

#define B 4
#define C 256
#define NPTS 4096
#define KNN 5
#define C2 512

// ---------------- scratch (device globals: no allocation allowed) ----------
__device__ float d_xx[B*NPTS];               // squared norms per point
__device__ float d_WcT[C*C2];                // [c][j]  j<256: W1 row j ; j>=256: (W2-W1) row j-256
__device__ float d_vu[B*NPTS*C2];            // [b][m][j]  j<256: v ; j>=256: u
__device__ int   d_idx[B*NPTS*KNN];          // knn indices
__device__ float d_psum [256*C];             // per-block partial BN sums
__device__ float d_psum2[256*C];
__device__ float d_scale[C];
__device__ float d_shift[C];

// ---------------- prep: xx = sum_c x^2 ------------------------------------
__global__ void prep_xx(const float* __restrict__ x) {
    int b = blockIdx.y;
    int n = blockIdx.x*256 + threadIdx.x;
    const float* xb = x + b*C*NPTS + n;
    float s = 0.f;
    #pragma unroll 8
    for (int c = 0; c < C; c++) { float v = xb[c*NPTS]; s = fmaf(v, v, s); }
    d_xx[b*NPTS + n] = s;
}

// ---------------- prep: stacked, transposed weight -------------------------
// WcT[c][j] : j<256 -> W[j][c] ; j>=256 -> W[j-256][256+c] - W[j-256][c]
__global__ void prep_w(const float* __restrict__ W) {
    int e = blockIdx.x*256 + threadIdx.x;     // e < 256*512
    int c = e >> 9, j = e & 511;
    float v;
    if (j < 256) v = W[j*C2 + c];
    else { int o = j - 256; v = W[o*C2 + 256 + c] - W[o*C2 + c]; }
    d_WcT[e] = v;
}

// ---------------- KNN: tiled pairwise GEMM + streaming top-5 ---------------
// grid (NPTS/64, B), 256 threads. Tile: 64 rows(n) x 64 cols(m), K-chunk 16.
// Thread (ty,tx) owns rows n0+4ty..+3, cols {m0+4tx..+3}. Per-thread top-5
// over its column subset; merged per row at the end (80 candidates).
__global__ void __launch_bounds__(256, 2) knn_kernel(const float* __restrict__ x) {
    __shared__ __align__(16) unsigned char sraw[41472];
    float (*As)[64]    = (float (*)[64]) sraw;             // 4 KB  [k][n]
    float (*Bs)[64]    = (float (*)[64])(sraw + 4096);     // 4 KB  [k][m]
    float *xxm_s       = (float*)(sraw + 8192);            // 256 B
    float (*candV)[81] = (float (*)[81]) sraw;             // 20.25 KB (aliases GEMM smem)
    int   (*candI)[81] = (int   (*)[81])(sraw + 20736);    // 20.25 KB

    int b   = blockIdx.y;
    int n0  = blockIdx.x * 64;
    int tid = threadIdx.x;
    int tx  = tid & 15, ty = tid >> 4;
    const float* xb = x + b*C*NPTS;

    float xxn_r[4];
    #pragma unroll
    for (int r = 0; r < 4; r++) xxn_r[r] = d_xx[b*NPTS + n0 + 4*ty + r];

    float tv[4][5]; int tix[4][5];
    #pragma unroll
    for (int r = 0; r < 4; r++)
        #pragma unroll
        for (int j = 0; j < 5; j++) { tv[r][j] = -CUDART_INF_F; tix[r][j] = 0; }

    for (int m0 = 0; m0 < NPTS; m0 += 64) {
        float acc[4][4] = {};
        for (int c0 = 0; c0 < C; c0 += 16) {
            __syncthreads();   // protects prior-iter As/Bs reads and xxm_s reads
            if (c0 == 0 && tid < 64) xxm_s[tid] = d_xx[b*NPTS + m0 + tid];
            #pragma unroll
            for (int i = 0; i < 4; i++) {
                int e = tid + 256*i;
                int kk = e >> 6, col = e & 63;
                As[kk][col] = xb[(c0+kk)*NPTS + n0 + col];
                Bs[kk][col] = xb[(c0+kk)*NPTS + m0 + col];
            }
            __syncthreads();
            #pragma unroll
            for (int kk = 0; kk < 16; kk++) {
                float4 a4 = *(const float4*)&As[kk][4*ty];
                float4 b4 = *(const float4*)&Bs[kk][4*tx];
                float a[4] = {a4.x, a4.y, a4.z, a4.w};
                float bb[4] = {b4.x, b4.y, b4.z, b4.w};
                #pragma unroll
                for (int r = 0; r < 4; r++)
                    #pragma unroll
                    for (int c = 0; c < 4; c++)
                        acc[r][c] = fmaf(a[r], bb[c], acc[r][c]);
            }
        }
        // pairwise + streaming top-5 insert
        float xxm_r[4];
        #pragma unroll
        for (int c = 0; c < 4; c++) xxm_r[c] = xxm_s[4*tx + c];
        #pragma unroll
        for (int r = 0; r < 4; r++) {
            #pragma unroll
            for (int c = 0; c < 4; c++) {
                float pw = 2.f*acc[r][c] - xxn_r[r] - xxm_r[c];
                if (pw > tv[r][4]) {
                    float v = pw; int ii = m0 + 4*tx + c;
                    #pragma unroll
                    for (int j = 0; j < 5; j++) {      // sorted (desc) insert
                        bool gt = v > tv[r][j];
                        float ov = tv[r][j]; int oi = tix[r][j];
                        tv[r][j]  = gt ? v  : ov;
                        tix[r][j] = gt ? ii : oi;
                        v  = gt ? ov : v;
                        ii = gt ? oi : ii;
                    }
                }
            }
        }
    }

    // merge: 16 threads x 5 candidates per row -> top-5
    __syncthreads();
    #pragma unroll
    for (int r = 0; r < 4; r++) {
        int row = 4*ty + r;
        #pragma unroll
        for (int j = 0; j < 5; j++) {
            candV[row][tx*5 + j] = tv[r][j];
            candI[row][tx*5 + j] = tix[r][j];
        }
    }
    __syncthreads();
    if (tid < 64) {
        int n = n0 + tid;
        #pragma unroll
        for (int s = 0; s < 5; s++) {
            float best = -CUDART_INF_F; int bi = 0;
            for (int e = 0; e < 80; e++) {
                float v = candV[tid][e];
                if (v > best) { best = v; bi = e; }
            }
            d_idx[(b*NPTS + n)*KNN + s] = candI[tid][bi];
            candV[tid][bi] = -CUDART_INF_F;
        }
    }
}

// ---------------- vu = [W1; W2-W1] @ x  (output (b, m, j), j contiguous) ---
__global__ void __launch_bounds__(256) vu_gemm(const float* __restrict__ x) {
    __shared__ float As[16][64];   // x    [k][m]
    __shared__ float Bs[16][64];   // WcT  [k][j]
    int b  = blockIdx.z;
    int m0 = blockIdx.x * 64;
    int j0 = blockIdx.y * 64;
    int tid = threadIdx.x, tx = tid & 15, ty = tid >> 4;
    const float* xb = x + b*C*NPTS;

    float acc[4][4] = {};
    for (int c0 = 0; c0 < C; c0 += 16) {
        __syncthreads();
        #pragma unroll
        for (int i = 0; i < 4; i++) {
            int e = tid + 256*i;
            int kk = e >> 6, col = e & 63;
            As[kk][col] = xb[(c0+kk)*NPTS + m0 + col];
            Bs[kk][col] = d_WcT[(c0+kk)*C2 + j0 + col];
        }
        __syncthreads();
        #pragma unroll
        for (int kk = 0; kk < 16; kk++) {
            float4 a4 = *(const float4*)&As[kk][4*ty];
            float4 b4 = *(const float4*)&Bs[kk][4*tx];
            float a[4] = {a4.x, a4.y, a4.z, a4.w};
            float bb[4] = {b4.x, b4.y, b4.z, b4.w};
            #pragma unroll
            for (int r = 0; r < 4; r++)
                #pragma unroll
                for (int c = 0; c < 4; c++)
                    acc[r][c] = fmaf(a[r], bb[c], acc[r][c]);
        }
    }
    #pragma unroll
    for (int r = 0; r < 4; r++) {
        int m = m0 + 4*ty + r;
        float4 o4 = make_float4(acc[r][0], acc[r][1], acc[r][2], acc[r][3]);
        *(float4*)&d_vu[(b*NPTS + m)*C2 + j0 + 4*tx] = o4;
    }
}

// ---------------- BN stats: sum / sumsq of y = v[idx] + u  (deterministic) -
__global__ void __launch_bounds__(256) stats_kernel() {
    int b  = blockIdx.y;
    int n0 = blockIdx.x * 64;
    int o  = threadIdx.x;
    float s = 0.f, s2 = 0.f;
    for (int nl = 0; nl < 64; nl++) {
        int n = n0 + nl;
        const float* vun = d_vu + (b*NPTS + n)*C2;
        float u = vun[256 + o];
        const int* ip = d_idx + (b*NPTS + n)*KNN;
        #pragma unroll
        for (int k = 0; k < KNN; k++) {
            int m = ip[k];
            float y = d_vu[(b*NPTS + m)*C2 + o] + u;
            s += y;
            s2 = fmaf(y, y, s2);
        }
    }
    int pb = blockIdx.y*64 + blockIdx.x;   // 0..255
    d_psum [pb*C + o] = s;
    d_psum2[pb*C + o] = s2;
}

__global__ void bn_finalize(const float* __restrict__ gamma, const float* __restrict__ beta) {
    int o = threadIdx.x;
    float s = 0.f, s2 = 0.f;
    for (int pb = 0; pb < 256; pb++) { s += d_psum[pb*C + o]; s2 += d_psum2[pb*C + o]; }
    float cnt  = (float)(B*NPTS*KNN);
    float mean = s / cnt;
    float var  = s2 / cnt - mean*mean;
    float sc   = gamma[o] * rsqrtf(var + 1e-5f);
    d_scale[o] = sc;
    d_shift[o] = beta[o] - mean*sc;
}

// ---------------- final: relu(max_k(bn(y))) + x, transposed write ----------
__global__ void __launch_bounds__(256) final_kernel(const float* __restrict__ x,
                                                    float* __restrict__ out) {
    __shared__ float res[256][33];
    int b = blockIdx.y, n0 = blockIdx.x*32;
    int o = threadIdx.x;
    float sc = d_scale[o], sh = d_shift[o];
    for (int nl = 0; nl < 32; nl++) {
        int n = n0 + nl;
        const float* vun = d_vu + (b*NPTS + n)*C2;
        float u  = vun[256 + o];
        float cc = fmaf(u, sc, sh);                 // (v+u)*sc+sh = v*sc + cc
        const int* ip = d_idx + (b*NPTS + n)*KNN;
        float mx = -CUDART_INF_F;
        #pragma unroll
        for (int k = 0; k < KNN; k++) {
            float v = d_vu[(b*NPTS + ip[k])*C2 + o];
            mx = fmaxf(mx, fmaf(v, sc, cc));
        }
        res[o][nl] = fmaxf(mx, 0.f);                // relu(max) == max(relu)
    }
    __syncthreads();
    int lane = threadIdx.x & 31, og = threadIdx.x >> 5;
    #pragma unroll 4
    for (int p = 0; p < 32; p++) {
        int oo = p*8 + og;
        int gi = (b*C + oo)*NPTS + n0 + lane;
        out[gi] = res[oo][lane] + x[gi];
    }
}

// ---------------- launch ---------------------------------------------------
extern "C" void kernel_launch(void* const* d_in, const int* in_sizes, int n_in,
                              void* d_out, int out_size) {
    const float* x     = (const float*)d_in[0];
    const float* W     = (const float*)d_in[1];
    const float* gamma = (const float*)d_in[2];
    const float* beta  = (const float*)d_in[3];
    float* out = (float*)d_out;

    prep_xx    <<<dim3(NPTS/256, B), 256>>>(x);
    prep_w     <<<dim3(C*C2/256), 256>>>(W);
    knn_kernel <<<dim3(NPTS/64, B), 256>>>(x);
    vu_gemm    <<<dim3(NPTS/64, C2/64, B), 256>>>(x);
    stats_kernel<<<dim3(NPTS/64, B), 256>>>();
    bn_finalize<<<1, 256>>>(gamma, beta);
    final_kernel<<<dim3(NPTS/32, B), 256>>>(x, out);
}

// round 5
// speedup vs baseline: 2.5232x; 2.5232x over previous
#include <cuda_runtime.h>
#include <cuda_bf16.h>
#include <math_constants.h>
#include <cstdint>

#define B 4
#define C 256
#define NPTS 4096
#define KNN 5
#define C2 512
#define KHW 512   // bf16 halfwords per point row (hi 256 | lo 256)

// ---------------- scratch (device globals: no allocation allowed) ----------
__device__ float d_xx[B*NPTS];
__device__ float d_WcT[C*C2];
__device__ float d_vu[B*NPTS*C2];
__device__ int   d_idx[B*NPTS*KNN];
__device__ int   d_cand[B*NPTS*8];                   // top-7 approx candidates
__device__ float d_psum [256*C];
__device__ float d_psum2[256*C];
__device__ float d_scale[C];
__device__ float d_shift[C];
__device__ __align__(16) uint16_t d_xs[B*NPTS*KHW];  // [b][n][k] bf16 split
__device__ __align__(16) float d_xt[B*NPTS*C];       // [b][n][c] fp32 row-major

// ---------------- baseline-PTX helpers (NO tcgen05 anywhere) ---------------
__device__ __forceinline__ uint32_t smem_u32(const void* p) {
    uint32_t a;
    asm("{ .reg .u64 t; cvta.to.shared.u64 t, %1; cvt.u32.u64 %0, t; }" : "=r"(a) : "l"(p));
    return a;
}
__device__ __forceinline__ void cp16(uint32_t dst, const void* src) {
    asm volatile("cp.async.cg.shared.global [%0], [%1], 16;" :: "r"(dst), "l"(src) : "memory");
}
#define CP_COMMIT() asm volatile("cp.async.commit_group;" ::: "memory")
#define CP_WAIT1()  asm volatile("cp.async.wait_group 1;" ::: "memory")
#define CP_WAIT0()  asm volatile("cp.async.wait_group 0;" ::: "memory")

__device__ __forceinline__ void ldsm4(uint32_t& r0, uint32_t& r1, uint32_t& r2, uint32_t& r3,
                                      uint32_t addr) {
    asm volatile("ldmatrix.sync.aligned.m8n8.x4.shared.b16 {%0,%1,%2,%3}, [%4];"
                 : "=r"(r0), "=r"(r1), "=r"(r2), "=r"(r3) : "r"(addr));
}
__device__ __forceinline__ void mma16816(float* c,
                                         uint32_t a0, uint32_t a1, uint32_t a2, uint32_t a3,
                                         uint32_t b0, uint32_t b1) {
    asm volatile("mma.sync.aligned.m16n8k16.row.col.f32.bf16.bf16.f32 "
                 "{%0,%1,%2,%3}, {%4,%5,%6,%7}, {%8,%9}, {%0,%1,%2,%3};"
                 : "+f"(c[0]), "+f"(c[1]), "+f"(c[2]), "+f"(c[3])
                 : "r"(a0), "r"(a1), "r"(a2), "r"(a3), "r"(b0), "r"(b1));
}

#define INS5(tv, ti) do { if (v > tv[4]) { float _v = v; int _i = ii;                 \
    _Pragma("unroll") for (int _q = 0; _q < 5; _q++) {                                \
        bool g = _v > tv[_q]; float ov = tv[_q]; int oi = ti[_q];                     \
        tv[_q] = g ? _v : ov; ti[_q] = g ? _i : oi;                                   \
        _v = g ? ov : _v; _i = g ? oi : _i; } } } while(0)

// ---------------- prep: xx = sum_c x^2 ------------------------------------
__global__ void prep_xx(const float* __restrict__ x) {
    int b = blockIdx.y;
    int n = blockIdx.x*256 + threadIdx.x;
    const float* xb = x + b*C*NPTS + n;
    float s = 0.f;
    #pragma unroll 8
    for (int c = 0; c < C; c++) { float v = xb[c*NPTS]; s = fmaf(v, v, s); }
    d_xx[b*NPTS + n] = s;
}

// ---------------- prep: stacked, transposed weight -------------------------
__global__ void prep_w(const float* __restrict__ W) {
    int e = blockIdx.x*256 + threadIdx.x;
    int c = e >> 9, j = e & 511;
    float v;
    if (j < 256) v = W[j*C2 + c];
    else { int o = j - 256; v = W[o*C2 + 256 + c] - W[o*C2 + c]; }
    d_WcT[e] = v;
}

// ------- prep: bf16 hi/lo split + fp32 transpose, both to [b][n][.] --------
__global__ void __launch_bounds__(256) prep_split(const float* __restrict__ x) {
    __shared__ float tile[64][65];
    int b = blockIdx.z, c0 = blockIdx.y*64, n0 = blockIdx.x*64;
    int tid = threadIdx.x;
    #pragma unroll
    for (int i = 0; i < 16; i++) {
        int e = tid + 256*i;
        int cl = e >> 6, nl = e & 63;
        tile[cl][nl] = x[(b*C + c0 + cl)*NPTS + n0 + nl];
    }
    __syncthreads();
    int nl = tid >> 2, cq = (tid & 3) * 16;
    uint16_t* oh = d_xs + ((size_t)(b*NPTS + n0 + nl))*KHW + c0 + cq;
    uint16_t* ol = oh + 256;
    float*    ot = d_xt + ((size_t)(b*NPTS + n0 + nl))*C + c0 + cq;
    #pragma unroll
    for (int j = 0; j < 16; j += 2) {
        float v0 = tile[cq+j][nl],  v1 = tile[cq+j+1][nl];
        __nv_bfloat16 h0 = __float2bfloat16(v0), h1 = __float2bfloat16(v1);
        __nv_bfloat16 l0 = __float2bfloat16(v0 - __bfloat162float(h0));
        __nv_bfloat16 l1 = __float2bfloat16(v1 - __bfloat162float(h1));
        *(uint32_t*)(oh + j) = (uint32_t)__bfloat16_as_ushort(h0) | ((uint32_t)__bfloat16_as_ushort(h1) << 16);
        *(uint32_t*)(ol + j) = (uint32_t)__bfloat16_as_ushort(l0) | ((uint32_t)__bfloat16_as_ushort(l1) << 16);
        *(float2*)(ot + j) = make_float2(v0, v1);
    }
}

// ---------------- KNN via HMMA (mma.sync bf16) + streaming top-5 -----------
// grid (32, B), 512 threads (16 warps). A: 128 rows x 512 hw resident in
// SMEM (stride 1040B). B: 128x128hw chunks, double-buffered cp.async.
// Approximate distances (hi.hi + lo.lo); exactness restored by verify_kernel.
#define NT 128
#define SMA   0                      // 128*1040 = 133120
#define SMB   133120                 // 2 * 34816 = 69632
#define SMBUF 34816                  // 128*272
#define SMXX  202752                 // 16384
#define SMTOT 219136
#define SMCV  SMB                    // merge buffers alias B
#define SMCI  (SMB + 20480)

__global__ void __launch_bounds__(512, 1) knn_mma() {
    extern __shared__ __align__(16) char smem[];
    uint32_t sb = smem_u32(smem);
    int b = blockIdx.y, n0 = blockIdx.x * NT;
    int tid = threadIdx.x, lane = tid & 31, wid = tid >> 5;
    int ngrp = wid >> 1, mhalf = wid & 1;
    const uint16_t* xsb = d_xs + (size_t)b*NPTS*KHW;

    #pragma unroll
    for (int i = 0; i < 16; i++) {
        int c = tid + 512*i; int row = c >> 6, col = c & 63;
        cp16(sb + SMA + row*1040 + col*16, xsb + (size_t)(n0+row)*KHW + col*8);
    }
    #pragma unroll
    for (int i = 0; i < 2; i++) {
        int c = tid + 512*i;
        cp16(sb + SMXX + c*16, d_xx + b*NPTS + c*4);
    }
    #pragma unroll
    for (int i = 0; i < 4; i++) {
        int c = tid + 512*i; int row = c >> 4, col = c & 15;
        cp16(sb + SMB + row*272 + col*16, xsb + (size_t)row*KHW + col*8);
    }
    CP_COMMIT();

    float tv0[5], tv1[5]; int ti0[5], ti1[5];
    #pragma unroll
    for (int j = 0; j < 5; j++) { tv0[j] = tv1[j] = -CUDART_INF_F; ti0[j] = ti1[j] = 0; }
    float acc[8][4];
    const float* xx_s = (const float*)(smem + SMXX);
    float xxn0 = 0.f, xxn1 = 0.f;

    int q = lane >> 3, l7 = lane & 7;
    uint32_t arow = sb + SMA + (ngrp*16 + (q & 1)*8 + l7) * 1040 + (q >> 1) * 16;
    uint32_t brow = (mhalf*64 + (q >> 1)*8 + l7) * 272 + (q & 1) * 16;

    for (int ci = 0; ci < 128; ci++) {
        int mt = ci >> 2, kc = ci & 3, buf = ci & 1;
        if (ci < 127) {
            int nmt = (ci+1) >> 2, nkc = (ci+1) & 3, nb = (ci+1) & 1;
            #pragma unroll
            for (int i = 0; i < 4; i++) {
                int c = tid + 512*i; int row = c >> 4, col = c & 15;
                cp16(sb + SMB + nb*SMBUF + row*272 + col*16,
                     xsb + (size_t)(nmt*128 + row)*KHW + nkc*128 + col*8);
            }
            CP_COMMIT();
            CP_WAIT1();
        } else {
            CP_WAIT0();
        }
        __syncthreads();
        if (ci == 0) {
            xxn0 = xx_s[n0 + ngrp*16 + (lane >> 2)];
            xxn1 = xx_s[n0 + ngrp*16 + (lane >> 2) + 8];
        }
        if (kc == 0) {
            #pragma unroll
            for (int t = 0; t < 8; t++)
                #pragma unroll
                for (int j = 0; j < 4; j++) acc[t][j] = 0.f;
        }
        uint32_t bb = sb + SMB + buf*SMBUF + brow;
        uint32_t aa = arow + kc*256;
        #pragma unroll
        for (int ks = 0; ks < 8; ks++) {
            uint32_t a0, a1, a2, a3;
            ldsm4(a0, a1, a2, a3, aa + ks*32);
            #pragma unroll
            for (int p = 0; p < 4; p++) {
                uint32_t b0, b1, b2, b3;
                ldsm4(b0, b1, b2, b3, bb + p*(16*272) + ks*32);
                mma16816(acc[2*p],   a0, a1, a2, a3, b0, b1);
                mma16816(acc[2*p+1], a0, a1, a2, a3, b2, b3);
            }
        }
        if (kc == 3) {
            int m0 = mt * 128;
            #pragma unroll
            for (int t = 0; t < 8; t++) {
                int cb = m0 + mhalf*64 + t*8 + 2*(lane & 3);
                float xm0 = xx_s[cb], xm1 = xx_s[cb + 1];
                float v; int ii;
                v = 2.f*acc[t][0] - xxn0 - xm0; ii = cb;     INS5(tv0, ti0);
                v = 2.f*acc[t][1] - xxn0 - xm1; ii = cb + 1; INS5(tv0, ti0);
                v = 2.f*acc[t][2] - xxn1 - xm0; ii = cb;     INS5(tv1, ti1);
                v = 2.f*acc[t][3] - xxn1 - xm1; ii = cb + 1; INS5(tv1, ti1);
            }
        }
        __syncthreads();
    }

    // merge: per row, 40 candidates -> approx top-7 for fp32 verify
    float* cv  = (float*)(smem + SMCV);
    int*   cix = (int*)  (smem + SMCI);
    int r0 = ngrp*16 + (lane >> 2);
    int slot = (mhalf*4 + (lane & 3)) * 5;
    #pragma unroll
    for (int j = 0; j < 5; j++) {
        cv [r0*40 + slot + j] = tv0[j];  cix[r0*40 + slot + j] = ti0[j];
        cv [(r0+8)*40 + slot + j] = tv1[j];  cix[(r0+8)*40 + slot + j] = ti1[j];
    }
    __syncthreads();
    if (tid < NT) {
        #pragma unroll
        for (int s = 0; s < 7; s++) {
            float best = -CUDART_INF_F; int bi = 0;
            for (int e = 0; e < 40; e++) {
                float v = cv[tid*40 + e];
                if (v > best) { best = v; bi = e; }
            }
            d_cand[(b*NPTS + n0 + tid)*8 + s] = cix[tid*40 + bi];
            cv[tid*40 + bi] = -CUDART_INF_F;
        }
    }
}

// -------- verify: exact fp32 re-rank of the 7 candidates, warp/point -------
__global__ void __launch_bounds__(128) verify_kernel() {
    int gw   = (blockIdx.x*128 + threadIdx.x) >> 5;   // global point id
    int lane = threadIdx.x & 31;
    int b = gw >> 12;
    const float* xq = d_xt + (size_t)gw*C;
    float4 q0 = ((const float4*)xq)[lane];
    float4 q1 = ((const float4*)xq)[lane + 32];
    float xxq = d_xx[gw];
    float pw[7]; int cid[7];
    #pragma unroll
    for (int k = 0; k < 7; k++) {
        int m = d_cand[gw*8 + k];
        cid[k] = m;
        const float* xc = d_xt + ((size_t)(b*NPTS + m))*C;
        float4 c0 = ((const float4*)xc)[lane];
        float4 c1 = ((const float4*)xc)[lane + 32];
        float s = 0.f;
        s = fmaf(q0.x, c0.x, s); s = fmaf(q0.y, c0.y, s);
        s = fmaf(q0.z, c0.z, s); s = fmaf(q0.w, c0.w, s);
        s = fmaf(q1.x, c1.x, s); s = fmaf(q1.y, c1.y, s);
        s = fmaf(q1.z, c1.z, s); s = fmaf(q1.w, c1.w, s);
        #pragma unroll
        for (int o = 16; o > 0; o >>= 1) s += __shfl_xor_sync(0xFFFFFFFFu, s, o);
        pw[k] = 2.f*s - xxq - d_xx[b*NPTS + m];
    }
    if (lane == 0) {
        #pragma unroll
        for (int s5 = 0; s5 < KNN; s5++) {
            float best = -CUDART_INF_F; int bi = 0;
            #pragma unroll
            for (int e = 0; e < 7; e++) if (pw[e] > best) { best = pw[e]; bi = e; }
            d_idx[gw*KNN + s5] = cid[bi];
            pw[bi] = -CUDART_INF_F;
        }
    }
}

// ---------------- vu = [W1; W2-W1] @ x  (output (b, m, j), j contiguous) ---
__global__ void __launch_bounds__(256) vu_gemm(const float* __restrict__ x) {
    __shared__ float As[16][64];
    __shared__ float Bs[16][64];
    int b  = blockIdx.z;
    int m0 = blockIdx.x * 64;
    int j0 = blockIdx.y * 64;
    int tid = threadIdx.x, tx = tid & 15, ty = tid >> 4;
    const float* xb = x + b*C*NPTS;

    float acc[4][4] = {};
    for (int c0 = 0; c0 < C; c0 += 16) {
        __syncthreads();
        #pragma unroll
        for (int i = 0; i < 4; i++) {
            int e = tid + 256*i;
            int kk = e >> 6, col = e & 63;
            As[kk][col] = xb[(c0+kk)*NPTS + m0 + col];
            Bs[kk][col] = d_WcT[(c0+kk)*C2 + j0 + col];
        }
        __syncthreads();
        #pragma unroll
        for (int kk = 0; kk < 16; kk++) {
            float4 a4 = *(const float4*)&As[kk][4*ty];
            float4 b4 = *(const float4*)&Bs[kk][4*tx];
            float a[4] = {a4.x, a4.y, a4.z, a4.w};
            float bb[4] = {b4.x, b4.y, b4.z, b4.w};
            #pragma unroll
            for (int r = 0; r < 4; r++)
                #pragma unroll
                for (int c = 0; c < 4; c++)
                    acc[r][c] = fmaf(a[r], bb[c], acc[r][c]);
        }
    }
    #pragma unroll
    for (int r = 0; r < 4; r++) {
        int m = m0 + 4*ty + r;
        float4 o4 = make_float4(acc[r][0], acc[r][1], acc[r][2], acc[r][3]);
        *(float4*)&d_vu[(b*NPTS + m)*C2 + j0 + 4*tx] = o4;
    }
}

// ---------------- BN stats ------------------------------------------------
__global__ void __launch_bounds__(256) stats_kernel() {
    int b  = blockIdx.y;
    int n0 = blockIdx.x * 64;
    int o  = threadIdx.x;
    float s = 0.f, s2 = 0.f;
    for (int nl = 0; nl < 64; nl++) {
        int n = n0 + nl;
        const float* vun = d_vu + (b*NPTS + n)*C2;
        float u = vun[256 + o];
        const int* ip = d_idx + (b*NPTS + n)*KNN;
        #pragma unroll
        for (int k = 0; k < KNN; k++) {
            int m = ip[k];
            float y = d_vu[(b*NPTS + m)*C2 + o] + u;
            s += y;
            s2 = fmaf(y, y, s2);
        }
    }
    int pb = blockIdx.y*64 + blockIdx.x;
    d_psum [pb*C + o] = s;
    d_psum2[pb*C + o] = s2;
}

__global__ void bn_finalize(const float* __restrict__ gamma, const float* __restrict__ beta) {
    int o = threadIdx.x;
    float s = 0.f, s2 = 0.f;
    for (int pb = 0; pb < 256; pb++) { s += d_psum[pb*C + o]; s2 += d_psum2[pb*C + o]; }
    float cnt  = (float)(B*NPTS*KNN);
    float mean = s / cnt;
    float var  = s2 / cnt - mean*mean;
    float sc   = gamma[o] * rsqrtf(var + 1e-5f);
    d_scale[o] = sc;
    d_shift[o] = beta[o] - mean*sc;
}

// ---------------- final ---------------------------------------------------
__global__ void __launch_bounds__(256) final_kernel(const float* __restrict__ x,
                                                    float* __restrict__ out) {
    __shared__ float res[256][33];
    int b = blockIdx.y, n0 = blockIdx.x*32;
    int o = threadIdx.x;
    float sc = d_scale[o], sh = d_shift[o];
    for (int nl = 0; nl < 32; nl++) {
        int n = n0 + nl;
        const float* vun = d_vu + (b*NPTS + n)*C2;
        float u  = vun[256 + o];
        float cc = fmaf(u, sc, sh);
        const int* ip = d_idx + (b*NPTS + n)*KNN;
        float mx = -CUDART_INF_F;
        #pragma unroll
        for (int k = 0; k < KNN; k++) {
            float v = d_vu[(b*NPTS + ip[k])*C2 + o];
            mx = fmaxf(mx, fmaf(v, sc, cc));
        }
        res[o][nl] = fmaxf(mx, 0.f);
    }
    __syncthreads();
    int lane = threadIdx.x & 31, og = threadIdx.x >> 5;
    #pragma unroll 4
    for (int p = 0; p < 32; p++) {
        int oo = p*8 + og;
        int gi = (b*C + oo)*NPTS + n0 + lane;
        out[gi] = res[oo][lane] + x[gi];
    }
}

// ---------------- launch ---------------------------------------------------
extern "C" void kernel_launch(void* const* d_in, const int* in_sizes, int n_in,
                              void* d_out, int out_size) {
    const float* x     = (const float*)d_in[0];
    const float* W     = (const float*)d_in[1];
    const float* gamma = (const float*)d_in[2];
    const float* beta  = (const float*)d_in[3];
    float* out = (float*)d_out;

    cudaFuncSetAttribute(knn_mma, cudaFuncAttributeMaxDynamicSharedMemorySize, SMTOT);

    prep_xx      <<<dim3(NPTS/256, B), 256>>>(x);
    prep_w       <<<dim3(C*C2/256), 256>>>(W);
    prep_split   <<<dim3(NPTS/64, C/64, B), 256>>>(x);
    knn_mma      <<<dim3(NPTS/NT, B), 512, SMTOT>>>();
    verify_kernel<<<dim3(B*NPTS/4), 128>>>();
    vu_gemm      <<<dim3(NPTS/64, C2/64, B), 256>>>(x);
    stats_kernel <<<dim3(NPTS/64, B), 256>>>();
    bn_finalize  <<<1, 256>>>(gamma, beta);
    final_kernel <<<dim3(NPTS/32, B), 256>>>(x, out);
}

// round 6
// speedup vs baseline: 3.8351x; 1.5199x over previous
#include <cuda_runtime.h>
#include <cuda_bf16.h>
#include <math_constants.h>
#include <cstdint>

#define B 4
#define C 256
#define NPTS 4096
#define KNN 5
#define C2 512
#define KHW 512   // d_xs halfwords per point row (hi 256 | lo 256)

// ---------------- scratch (device globals: no allocation allowed) ----------
__device__ float d_xx[B*NPTS];
__device__ float d_vu[B*NPTS*C2];
__device__ int   d_idx[B*NPTS*KNN];
__device__ int   d_cand[B*NPTS*8];                   // top-7 approx candidates
__device__ float d_psum [256*C];
__device__ float d_psum2[256*C];
__device__ float d_scale[C];
__device__ float d_shift[C];
__device__ __align__(16) uint16_t d_xs[B*NPTS*KHW];  // [b][n][k] bf16 hi|lo
__device__ __align__(16) float d_xt[B*NPTS*C];       // [b][n][c] fp32 row-major
__device__ __align__(16) uint16_t d_Ws[C2*768];      // [j][k] bf16: Whi|Whi|Wlo

// ---------------- baseline-PTX helpers (NO tcgen05 anywhere) ---------------
__device__ __forceinline__ uint32_t smem_u32(const void* p) {
    uint32_t a;
    asm("{ .reg .u64 t; cvta.to.shared.u64 t, %1; cvt.u32.u64 %0, t; }" : "=r"(a) : "l"(p));
    return a;
}
__device__ __forceinline__ void cp16(uint32_t dst, const void* src) {
    asm volatile("cp.async.cg.shared.global [%0], [%1], 16;" :: "r"(dst), "l"(src) : "memory");
}
#define CP_COMMIT() asm volatile("cp.async.commit_group;" ::: "memory")
#define CP_WAIT1()  asm volatile("cp.async.wait_group 1;" ::: "memory")

__device__ __forceinline__ void ldsm4(uint32_t& r0, uint32_t& r1, uint32_t& r2, uint32_t& r3,
                                      uint32_t addr) {
    asm volatile("ldmatrix.sync.aligned.m8n8.x4.shared.b16 {%0,%1,%2,%3}, [%4];"
                 : "=r"(r0), "=r"(r1), "=r"(r2), "=r"(r3) : "r"(addr));
}
__device__ __forceinline__ void mma16816(float* c,
                                         uint32_t a0, uint32_t a1, uint32_t a2, uint32_t a3,
                                         uint32_t b0, uint32_t b1) {
    asm volatile("mma.sync.aligned.m16n8k16.row.col.f32.bf16.bf16.f32 "
                 "{%0,%1,%2,%3}, {%4,%5,%6,%7}, {%8,%9}, {%0,%1,%2,%3};"
                 : "+f"(c[0]), "+f"(c[1]), "+f"(c[2]), "+f"(c[3])
                 : "r"(a0), "r"(a1), "r"(a2), "r"(a3), "r"(b0), "r"(b1));
}

#define INS5(tv, ti) do { if (v > tv[4]) { float _v = v; int _i = ii;                 \
    _Pragma("unroll") for (int _q = 0; _q < 5; _q++) {                                \
        bool g = _v > tv[_q]; float ov = tv[_q]; int oi = ti[_q];                     \
        tv[_q] = g ? _v : ov; ti[_q] = g ? _i : oi;                                   \
        _v = g ? ov : _v; _i = g ? oi : _i; } } } while(0)

// ---------------- prep: xx = sum_c x^2 ------------------------------------
__global__ void prep_xx(const float* __restrict__ x) {
    int b = blockIdx.y;
    int n = blockIdx.x*256 + threadIdx.x;
    const float* xb = x + b*C*NPTS + n;
    float s = 0.f;
    #pragma unroll 8
    for (int c = 0; c < C; c++) { float v = xb[c*NPTS]; s = fmaf(v, v, s); }
    d_xx[b*NPTS + n] = s;
}

// --------- prep: stacked bf16 weights Ws[j][k] = Whi | Whi | Wlo -----------
__global__ void prep_wbf(const float* __restrict__ W) {
    int e = blockIdx.x*256 + threadIdx.x;       // e < 512*256
    int j = e >> 8, c = e & 255;
    float w;
    if (j < 256) w = W[j*C2 + c];
    else { int o = j - 256; w = W[o*C2 + 256 + c] - W[o*C2 + c]; }
    __nv_bfloat16 hi = __float2bfloat16(w);
    __nv_bfloat16 lo = __float2bfloat16(w - __bfloat162float(hi));
    uint16_t hb = __bfloat16_as_ushort(hi), lb = __bfloat16_as_ushort(lo);
    d_Ws[(size_t)j*768 + c]       = hb;
    d_Ws[(size_t)j*768 + 256 + c] = hb;
    d_Ws[(size_t)j*768 + 512 + c] = lb;
}

// ------- prep: bf16 hi/lo split + fp32 transpose, both to [b][n][.] --------
__global__ void __launch_bounds__(256) prep_split(const float* __restrict__ x) {
    __shared__ float tile[64][65];
    int b = blockIdx.z, c0 = blockIdx.y*64, n0 = blockIdx.x*64;
    int tid = threadIdx.x;
    #pragma unroll
    for (int i = 0; i < 16; i++) {
        int e = tid + 256*i;
        int cl = e >> 6, nl = e & 63;
        tile[cl][nl] = x[(b*C + c0 + cl)*NPTS + n0 + nl];
    }
    __syncthreads();
    int nl = tid >> 2, cq = (tid & 3) * 16;
    uint16_t* oh = d_xs + ((size_t)(b*NPTS + n0 + nl))*KHW + c0 + cq;
    uint16_t* ol = oh + 256;
    float*    ot = d_xt + ((size_t)(b*NPTS + n0 + nl))*C + c0 + cq;
    #pragma unroll
    for (int j = 0; j < 16; j += 2) {
        float v0 = tile[cq+j][nl],  v1 = tile[cq+j+1][nl];
        __nv_bfloat16 h0 = __float2bfloat16(v0), h1 = __float2bfloat16(v1);
        __nv_bfloat16 l0 = __float2bfloat16(v0 - __bfloat162float(h0));
        __nv_bfloat16 l1 = __float2bfloat16(v1 - __bfloat162float(h1));
        *(uint32_t*)(oh + j) = (uint32_t)__bfloat16_as_ushort(h0) | ((uint32_t)__bfloat16_as_ushort(h1) << 16);
        *(uint32_t*)(ol + j) = (uint32_t)__bfloat16_as_ushort(l0) | ((uint32_t)__bfloat16_as_ushort(l1) << 16);
        *(float2*)(ot + j) = make_float2(v0, v1);
    }
}

// ---------------- KNN via HMMA, K=256 (hi only) ----------------------------
// grid (32, B), 256 threads / 8 warps. Warp tile 32 rows x 64 cols.
// A: 128 rows x 256hw resident. B: full-K 128-row chunks, double-buffered.
#define SMA   0                      // 128*528 = 67584
#define SMB   67584                  // 2 * 67584
#define SMBUF 67584
#define SMXX  202752                 // 16384
#define SMTOT 219136
#define SMCV  SMB                    // merge buffers alias B buf0
#define SMCI  (SMB + 20480)

__global__ void __launch_bounds__(256, 1) knn_mma() {
    extern __shared__ __align__(16) char smem[];
    uint32_t sb = smem_u32(smem);
    int b = blockIdx.y, n0 = blockIdx.x * 128;
    int tid = threadIdx.x, lane = tid & 31, wid = tid >> 5;
    int ngrp = wid >> 1, mhalf = wid & 1;
    const uint16_t* xsb = d_xs + (size_t)b*NPTS*KHW;

    // group0: A (first 256 hw) + xx + B chunk 0
    #pragma unroll
    for (int i = 0; i < 16; i++) {
        int c = tid + 256*i; int row = c >> 5, col = c & 31;
        cp16(sb + SMA + row*528 + col*16, xsb + (size_t)(n0+row)*KHW + col*8);
    }
    #pragma unroll
    for (int i = 0; i < 4; i++) {
        int c = tid + 256*i;
        cp16(sb + SMXX + c*16, d_xx + b*NPTS + c*4);
    }
    #pragma unroll
    for (int i = 0; i < 16; i++) {
        int c = tid + 256*i; int row = c >> 5, col = c & 31;
        cp16(sb + SMB + row*528 + col*16, xsb + (size_t)row*KHW + col*8);
    }
    CP_COMMIT();
    // group1: B chunk 1
    #pragma unroll
    for (int i = 0; i < 16; i++) {
        int c = tid + 256*i; int row = c >> 5, col = c & 31;
        cp16(sb + SMB + SMBUF + row*528 + col*16, xsb + (size_t)(128+row)*KHW + col*8);
    }
    CP_COMMIT();

    float tv[4][5]; int tix[4][5];
    #pragma unroll
    for (int L = 0; L < 4; L++)
        #pragma unroll
        for (int j = 0; j < 5; j++) { tv[L][j] = -CUDART_INF_F; tix[L][j] = 0; }
    float xxn[4];
    const float* xx_s = (const float*)(smem + SMXX);

    int q = lane >> 3, l7 = lane & 7;
    uint32_t aoff = (uint32_t)((ngrp*32 + (q & 1)*8 + l7) * 528 + (q >> 1) * 16);
    uint32_t boff = (uint32_t)((mhalf*64 + (q >> 1)*8 + l7) * 528 + (q & 1) * 16);

    for (int mt = 0; mt < 32; mt++) {
        CP_WAIT1();
        __syncthreads();
        if (mt == 0) {
            #pragma unroll
            for (int L = 0; L < 4; L++)
                xxn[L] = xx_s[n0 + ngrp*32 + (L >> 1)*16 + (L & 1)*8 + (lane >> 2)];
        }
        float acc[2][8][4];
        #pragma unroll
        for (int ra = 0; ra < 2; ra++)
            #pragma unroll
            for (int t = 0; t < 8; t++)
                #pragma unroll
                for (int j = 0; j < 4; j++) acc[ra][t][j] = 0.f;

        uint32_t ba = sb + SMA + aoff;
        uint32_t bb = sb + SMB + (mt & 1)*SMBUF + boff;
        #pragma unroll
        for (int ks = 0; ks < 16; ks++) {
            uint32_t a0, a1, a2, a3, a4, a5, a6, a7;
            ldsm4(a0, a1, a2, a3, ba + ks*32);
            ldsm4(a4, a5, a6, a7, ba + 8448 + ks*32);
            #pragma unroll
            for (int p = 0; p < 4; p++) {
                uint32_t b0, b1, b2, b3;
                ldsm4(b0, b1, b2, b3, bb + p*8448 + ks*32);
                mma16816(acc[0][2*p],   a0, a1, a2, a3, b0, b1);
                mma16816(acc[0][2*p+1], a0, a1, a2, a3, b2, b3);
                mma16816(acc[1][2*p],   a4, a5, a6, a7, b0, b1);
                mma16816(acc[1][2*p+1], a4, a5, a6, a7, b2, b3);
            }
        }
        // epilogue: pairwise + streaming top-5
        int m0 = mt * 128;
        #pragma unroll
        for (int ra = 0; ra < 2; ra++) {
            #pragma unroll
            for (int t = 0; t < 8; t++) {
                int cb = m0 + mhalf*64 + t*8 + 2*(lane & 3);
                float xm0 = xx_s[cb], xm1 = xx_s[cb + 1];
                float v; int ii;
                v = 2.f*acc[ra][t][0] - xxn[2*ra]   - xm0; ii = cb;     INS5(tv[2*ra],   tix[2*ra]);
                v = 2.f*acc[ra][t][1] - xxn[2*ra]   - xm1; ii = cb + 1; INS5(tv[2*ra],   tix[2*ra]);
                v = 2.f*acc[ra][t][2] - xxn[2*ra+1] - xm0; ii = cb;     INS5(tv[2*ra+1], tix[2*ra+1]);
                v = 2.f*acc[ra][t][3] - xxn[2*ra+1] - xm1; ii = cb + 1; INS5(tv[2*ra+1], tix[2*ra+1]);
            }
        }
        __syncthreads();   // all warps done reading buffer mt&1
        if (mt + 2 < 32) {
            int nm = mt + 2;
            #pragma unroll
            for (int i = 0; i < 16; i++) {
                int c = tid + 256*i; int row = c >> 5, col = c & 31;
                cp16(sb + SMB + (mt & 1)*SMBUF + row*528 + col*16,
                     xsb + (size_t)(nm*128 + row)*KHW + col*8);
            }
        }
        CP_COMMIT();       // possibly-empty group keeps depth constant
    }

    // merge: per row 8 contributors x 5 = 40 candidates -> top-7
    float* cv  = (float*)(smem + SMCV);
    int*   cix = (int*)  (smem + SMCI);
    int slot = (mhalf*4 + (lane & 3)) * 5;
    #pragma unroll
    for (int L = 0; L < 4; L++) {
        int r = ngrp*32 + (L >> 1)*16 + (L & 1)*8 + (lane >> 2);
        #pragma unroll
        for (int j = 0; j < 5; j++) {
            cv [r*40 + slot + j] = tv[L][j];
            cix[r*40 + slot + j] = tix[L][j];
        }
    }
    __syncthreads();
    if (tid < 128) {
        #pragma unroll
        for (int s = 0; s < 7; s++) {
            float best = -CUDART_INF_F; int bi = 0;
            for (int e = 0; e < 40; e++) {
                float v = cv[tid*40 + e];
                if (v > best) { best = v; bi = e; }
            }
            d_cand[(b*NPTS + n0 + tid)*8 + s] = cix[tid*40 + bi];
            cv[tid*40 + bi] = -CUDART_INF_F;
        }
    }
}

// -------- verify: exact fp32 re-rank of the 7 candidates, warp/point -------
__global__ void __launch_bounds__(128) verify_kernel() {
    int gw   = (blockIdx.x*128 + threadIdx.x) >> 5;
    int lane = threadIdx.x & 31;
    int b = gw >> 12;
    const float* xq = d_xt + (size_t)gw*C;
    float4 q0 = ((const float4*)xq)[lane];
    float4 q1 = ((const float4*)xq)[lane + 32];
    float xxq = d_xx[gw];
    float pw[7]; int cid[7];
    #pragma unroll
    for (int k = 0; k < 7; k++) {
        int m = d_cand[gw*8 + k];
        cid[k] = m;
        const float* xc = d_xt + ((size_t)(b*NPTS + m))*C;
        float4 c0 = ((const float4*)xc)[lane];
        float4 c1 = ((const float4*)xc)[lane + 32];
        float s = 0.f;
        s = fmaf(q0.x, c0.x, s); s = fmaf(q0.y, c0.y, s);
        s = fmaf(q0.z, c0.z, s); s = fmaf(q0.w, c0.w, s);
        s = fmaf(q1.x, c1.x, s); s = fmaf(q1.y, c1.y, s);
        s = fmaf(q1.z, c1.z, s); s = fmaf(q1.w, c1.w, s);
        #pragma unroll
        for (int o = 16; o > 0; o >>= 1) s += __shfl_xor_sync(0xFFFFFFFFu, s, o);
        pw[k] = 2.f*s - xxq - d_xx[b*NPTS + m];
    }
    if (lane == 0) {
        #pragma unroll
        for (int s5 = 0; s5 < KNN; s5++) {
            float best = -CUDART_INF_F; int bi = 0;
            #pragma unroll
            for (int e = 0; e < 7; e++) if (pw[e] > best) { best = pw[e]; bi = e; }
            d_idx[gw*KNN + s5] = cid[bi];
            pw[bi] = -CUDART_INF_F;
        }
    }
}

// ------- vu = Ws @ x via HMMA 3-term split (K=768), out (b, m, j) ----------
// grid (32, 4, B), 256 threads / 8 warps, CTA tile 128m x 128j.
// k-chunks of 64 hw, double-buffered. A k-map: chunk<8 -> d_xs[k], else hi again.
#define VBUF 36864    // per buffer: As 128*144=18432 + Bs 18432
#define VSMT 73728

__global__ void __launch_bounds__(256) vu_mma() {
    extern __shared__ __align__(16) char smem[];
    uint32_t sb = smem_u32(smem);
    int b = blockIdx.z, m0 = blockIdx.x*128, j0 = blockIdx.y*128;
    int tid = threadIdx.x, lane = tid & 31, wid = tid >> 5;
    int ngrp = wid >> 1, mhalf = wid & 1;

    int q = lane >> 3, l7 = lane & 7;
    uint32_t aoff = (uint32_t)((ngrp*32 + (q & 1)*8 + l7) * 144 + (q >> 1) * 16);
    uint32_t boff = (uint32_t)(18432 + (mhalf*64 + (q >> 1)*8 + l7) * 144 + (q & 1) * 16);

    // issue chunk 0, chunk 1
    #pragma unroll
    for (int pc = 0; pc < 2; pc++) {
        int koff = pc * 64;   // chunks 0,1 are in hi region
        #pragma unroll
        for (int i = 0; i < 4; i++) {
            int c = tid + 256*i; int row = c >> 3, col = c & 7;
            cp16(sb + pc*VBUF + row*144 + col*16,
                 d_xs + (size_t)(b*NPTS + m0 + row)*KHW + koff + col*8);
            cp16(sb + pc*VBUF + 18432 + row*144 + col*16,
                 d_Ws + (size_t)(j0 + row)*768 + pc*64 + col*8);
        }
        CP_COMMIT();
    }

    float acc[2][8][4];
    #pragma unroll
    for (int ra = 0; ra < 2; ra++)
        #pragma unroll
        for (int t = 0; t < 8; t++)
            #pragma unroll
            for (int j = 0; j < 4; j++) acc[ra][t][j] = 0.f;

    for (int kc = 0; kc < 12; kc++) {
        CP_WAIT1();
        __syncthreads();
        uint32_t ba = sb + (kc & 1)*VBUF;
        #pragma unroll
        for (int ks = 0; ks < 4; ks++) {
            uint32_t a0, a1, a2, a3, a4, a5, a6, a7;
            ldsm4(a0, a1, a2, a3, ba + aoff + ks*32);
            ldsm4(a4, a5, a6, a7, ba + aoff + 2304 + ks*32);
            #pragma unroll
            for (int p = 0; p < 4; p++) {
                uint32_t b0, b1, b2, b3;
                ldsm4(b0, b1, b2, b3, ba + boff + p*2304 + ks*32);
                mma16816(acc[0][2*p],   a0, a1, a2, a3, b0, b1);
                mma16816(acc[0][2*p+1], a0, a1, a2, a3, b2, b3);
                mma16816(acc[1][2*p],   a4, a5, a6, a7, b0, b1);
                mma16816(acc[1][2*p+1], a4, a5, a6, a7, b2, b3);
            }
        }
        __syncthreads();
        if (kc + 2 < 12) {
            int nc = kc + 2;
            int koff = (nc < 8) ? nc*64 : (nc - 8)*64;
            #pragma unroll
            for (int i = 0; i < 4; i++) {
                int c = tid + 256*i; int row = c >> 3, col = c & 7;
                cp16(sb + (kc & 1)*VBUF + row*144 + col*16,
                     d_xs + (size_t)(b*NPTS + m0 + row)*KHW + koff + col*8);
                cp16(sb + (kc & 1)*VBUF + 18432 + row*144 + col*16,
                     d_Ws + (size_t)(j0 + row)*768 + nc*64 + col*8);
            }
        }
        CP_COMMIT();
    }

    // write out
    #pragma unroll
    for (int ra = 0; ra < 2; ra++) {
        int r  = m0 + ngrp*32 + ra*16 + (lane >> 2);
        #pragma unroll
        for (int t = 0; t < 8; t++) {
            int cb = j0 + mhalf*64 + t*8 + 2*(lane & 3);
            *(float2*)&d_vu[(size_t)(b*NPTS + r)*C2 + cb]     = make_float2(acc[ra][t][0], acc[ra][t][1]);
            *(float2*)&d_vu[(size_t)(b*NPTS + r + 8)*C2 + cb] = make_float2(acc[ra][t][2], acc[ra][t][3]);
        }
    }
}

// ---------------- BN stats ------------------------------------------------
__global__ void __launch_bounds__(256) stats_kernel() {
    int b  = blockIdx.y;
    int n0 = blockIdx.x * 64;
    int o  = threadIdx.x;
    float s = 0.f, s2 = 0.f;
    for (int nl = 0; nl < 64; nl++) {
        int n = n0 + nl;
        const float* vun = d_vu + (size_t)(b*NPTS + n)*C2;
        float u = vun[256 + o];
        const int* ip = d_idx + (b*NPTS + n)*KNN;
        #pragma unroll
        for (int k = 0; k < KNN; k++) {
            int m = ip[k];
            float y = d_vu[(size_t)(b*NPTS + m)*C2 + o] + u;
            s += y;
            s2 = fmaf(y, y, s2);
        }
    }
    int pb = blockIdx.y*64 + blockIdx.x;
    d_psum [pb*C + o] = s;
    d_psum2[pb*C + o] = s2;
}

__global__ void bn_finalize(const float* __restrict__ gamma, const float* __restrict__ beta) {
    int o = threadIdx.x;
    float s = 0.f, s2 = 0.f;
    for (int pb = 0; pb < 256; pb++) { s += d_psum[pb*C + o]; s2 += d_psum2[pb*C + o]; }
    float cnt  = (float)(B*NPTS*KNN);
    float mean = s / cnt;
    float var  = s2 / cnt - mean*mean;
    float sc   = gamma[o] * rsqrtf(var + 1e-5f);
    d_scale[o] = sc;
    d_shift[o] = beta[o] - mean*sc;
}

// ---------------- final ---------------------------------------------------
__global__ void __launch_bounds__(256) final_kernel(const float* __restrict__ x,
                                                    float* __restrict__ out) {
    __shared__ float res[256][33];
    int b = blockIdx.y, n0 = blockIdx.x*32;
    int o = threadIdx.x;
    float sc = d_scale[o], sh = d_shift[o];
    for (int nl = 0; nl < 32; nl++) {
        int n = n0 + nl;
        const float* vun = d_vu + (size_t)(b*NPTS + n)*C2;
        float u  = vun[256 + o];
        float cc = fmaf(u, sc, sh);
        const int* ip = d_idx + (b*NPTS + n)*KNN;
        float mx = -CUDART_INF_F;
        #pragma unroll
        for (int k = 0; k < KNN; k++) {
            float v = d_vu[(size_t)(b*NPTS + ip[k])*C2 + o];
            mx = fmaxf(mx, fmaf(v, sc, cc));
        }
        res[o][nl] = fmaxf(mx, 0.f);
    }
    __syncthreads();
    int lane = threadIdx.x & 31, og = threadIdx.x >> 5;
    #pragma unroll 4
    for (int p = 0; p < 32; p++) {
        int oo = p*8 + og;
        int gi = (b*C + oo)*NPTS + n0 + lane;
        out[gi] = res[oo][lane] + x[gi];
    }
}

// ---------------- launch ---------------------------------------------------
extern "C" void kernel_launch(void* const* d_in, const int* in_sizes, int n_in,
                              void* d_out, int out_size) {
    const float* x     = (const float*)d_in[0];
    const float* W     = (const float*)d_in[1];
    const float* gamma = (const float*)d_in[2];
    const float* beta  = (const float*)d_in[3];
    float* out = (float*)d_out;

    cudaFuncSetAttribute(knn_mma, cudaFuncAttributeMaxDynamicSharedMemorySize, SMTOT);
    cudaFuncSetAttribute(vu_mma,  cudaFuncAttributeMaxDynamicSharedMemorySize, VSMT);

    prep_xx      <<<dim3(NPTS/256, B), 256>>>(x);
    prep_wbf     <<<dim3(C2*C/256), 256>>>(W);
    prep_split   <<<dim3(NPTS/64, C/64, B), 256>>>(x);
    knn_mma      <<<dim3(NPTS/128, B), 256, SMTOT>>>();
    verify_kernel<<<dim3(B*NPTS/4), 128>>>();
    vu_mma       <<<dim3(NPTS/128, C2/128, B), 256, VSMT>>>();
    stats_kernel <<<dim3(NPTS/64, B), 256>>>();
    bn_finalize  <<<1, 256>>>(gamma, beta);
    final_kernel <<<dim3(NPTS/32, B), 256>>>(x, out);
}